// round 7
// baseline (speedup 1.0000x reference)
#include <cuda_runtime.h>
#include <cstdint>

#define NN   16384
#define NE   262144
#define NG   16
#define CIN  128
#define CHID 256
#define CLAT 64

// ---- scratch (device globals; no allocation allowed) ----
__device__ float g_deg[NN];
__device__ float g_dinv[NN];
__device__ float g_aggx[NN * CIN];    // aggregated x (pre-transform)
__device__ float g_h[NN * CHID];      // relu hidden
__device__ float g_wT[CIN * CHID];    // gcn_w transposed  [k][h]
__device__ float g_linT[CHID * CLAT]; // lin_w transposed  [k][c]
__device__ float g_zsum[NG * CLAT];
__device__ float g_cnt[NG];
__device__ float g_gdec[NG * CIN];
__device__ float g_zhi[NN * CLAT];    // tf32 hi part of z_node
__device__ float g_zlo[NN * CLAT];    // tf32 lo part of z_node

// ---------------------------------------------------------
__global__ void k_init() {
    int i = blockIdx.x * blockDim.x + threadIdx.x;
    if (i < NN) g_deg[i] = 1.0f;          // self-loop
    if (i < NG * CLAT) g_zsum[i] = 0.0f;
    if (i < NG) g_cnt[i] = 0.0f;
}

__global__ void k_deg(const int* __restrict__ ei) {
    int e = blockIdx.x * blockDim.x + threadIdx.x;
    if (e < NE) atomicAdd(&g_deg[ei[NE + e]], 1.0f);
}

__global__ void k_dinv() {
    int i = blockIdx.x * blockDim.x + threadIdx.x;
    if (i < NN) g_dinv[i] = rsqrtf(g_deg[i]);
}

// self-loop term: aggx[i] = x[i] / deg[i]
__global__ void k_self(const float* __restrict__ x) {
    int idx = blockIdx.x * blockDim.x + threadIdx.x;
    if (idx < NN * CIN) g_aggx[idx] = x[idx] / g_deg[idx >> 7];
}

// edge scatter: one warp per edge, 4 channels/lane via red.global.add.v4.f32
__global__ void k_scatter(const float4* __restrict__ x4, const int* __restrict__ ei) {
    int gt = blockIdx.x * blockDim.x + threadIdx.x;
    int e = gt >> 5;
    int lane = gt & 31;
    if (e >= NE) return;
    int row = ei[e];
    int col = ei[NE + e];
    float norm = g_dinv[row] * g_dinv[col];
    float4 v = x4[row * 32 + lane];
    v.x *= norm; v.y *= norm; v.z *= norm; v.w *= norm;
    float* dst = &g_aggx[(col * 32 + lane) * 4];
    asm volatile("red.global.add.v4.f32 [%0], {%1, %2, %3, %4};"
                 :: "l"(dst), "f"(v.x), "f"(v.y), "f"(v.z), "f"(v.w) : "memory");
}

__global__ void k_wT(const float* __restrict__ gw, const float* __restrict__ lw) {
    int idx = blockIdx.x * blockDim.x + threadIdx.x;
    if (idx < CIN * CHID) {
        int h = idx >> 7, k = idx & 127;           // gcn_w [256][128]
        g_wT[k * CHID + h] = gw[idx];
    } else if (idx < CIN * CHID + CHID * CLAT) {
        int j = idx - CIN * CHID;
        int l = j >> 8, c = j & 255;               // lin_w [64][256]
        g_linT[c * CLAT + l] = lw[j];
    }
}

// h = relu(aggx @ gcn_w^T + gcn_b)   -- 4 nodes per block
__global__ void k_gcn(const float* __restrict__ gb) {
    __shared__ float sx[4][CIN];
    int i0 = blockIdx.x * 4;
    int t = threadIdx.x;
#pragma unroll
    for (int ii = 0; ii < 2; ii++) {
        int lin = t + ii * 256;
        sx[lin >> 7][lin & 127] = g_aggx[i0 * CIN + lin];
    }
    __syncthreads();
    float b = gb[t];
    float a0 = b, a1 = b, a2 = b, a3 = b;
#pragma unroll 4
    for (int k = 0; k < CIN; k++) {
        float w = g_wT[k * CHID + t];
        a0 += sx[0][k] * w;
        a1 += sx[1][k] * w;
        a2 += sx[2][k] * w;
        a3 += sx[3][k] * w;
    }
    g_h[(i0 + 0) * CHID + t] = fmaxf(a0, 0.f);
    g_h[(i0 + 1) * CHID + t] = fmaxf(a1, 0.f);
    g_h[(i0 + 2) * CHID + t] = fmaxf(a2, 0.f);
    g_h[(i0 + 3) * CHID + t] = fmaxf(a3, 0.f);
}

// z_node = h @ lin_w^T + lin_b  (+ graph pooling accumulation)
__global__ void k_z(const int* __restrict__ batch, const float* __restrict__ lb,
                    float* __restrict__ zout) {
    __shared__ float sA[4][CHID];
    int i0 = blockIdx.x * 4;
    int t = threadIdx.x;
#pragma unroll
    for (int ii = 0; ii < 4; ii++) {
        int lin = t + ii * 256;
        sA[lin >> 8][lin & 255] = g_h[i0 * CHID + lin];
    }
    __syncthreads();
    int j = t >> 6, c = t & 63;
    float acc = lb[c];
#pragma unroll 4
    for (int k = 0; k < CHID; k++) acc += sA[j][k] * g_linT[k * CLAT + c];
    int node = i0 + j;
    zout[node * CLAT + c] = acc;
    int b = batch[node];
    atomicAdd(&g_zsum[b * CLAT + c], acc);
    if (c == 0) atomicAdd(&g_cnt[b], 1.0f);
}

// split z into tf32 hi + tf32 lo (Markidis split for fp32-accurate tensor GEMM)
__global__ void k_split(const float* __restrict__ z) {
    int i = blockIdx.x * blockDim.x + threadIdx.x;
    if (i < NN * CLAT) {
        float v = z[i];
        uint32_t hb;
        asm("cvt.rna.tf32.f32 %0, %1;" : "=r"(hb) : "f"(v));
        float hi = __uint_as_float(hb);
        float lo = v - hi;
        uint32_t lb;
        asm("cvt.rna.tf32.f32 %0, %1;" : "=r"(lb) : "f"(lo));
        g_zhi[i] = hi;
        g_zlo[i] = __uint_as_float(lb);
    }
}

// z_graph + per-graph decoded row
__global__ void k_graph(const float* __restrict__ dw, const float* __restrict__ db,
                        float* __restrict__ zg_out) {
    __shared__ float zg[CLAT];
    int g = blockIdx.x, t = threadIdx.x;
    if (t < CLAT) {
        float cn = fmaxf(g_cnt[g], 1.0f);
        float v = g_zsum[g * CLAT + t] / cn;
        zg[t] = v;
        zg_out[g * CLAT + t] = v;
    }
    __syncthreads();
    float acc = db[t];
#pragma unroll
    for (int l = 0; l < CLAT; l++) acc += zg[l] * dw[t * CLAT + l];
    g_gdec[g * CIN + t] = acc;
}

__global__ void k_xhat(const int* __restrict__ batch, float* __restrict__ xo) {
    int idx = blockIdx.x * blockDim.x + threadIdx.x;
    if (idx < NN * CIN) {
        int i = idx >> 7;
        xo[idx] = g_gdec[batch[i] * CIN + (idx & 127)];
    }
}

// ---------------------------------------------------------
// a_hat = sigmoid(Z Z^T) on tensor cores: split-tf32, 3 mma passes.
// 128x128 tile per block (8 warps, warp grid 2x4, each warp 64x32).
// Symmetric: compute upper-tri tiles; mirror via SMEM transpose.
// ---------------------------------------------------------
__device__ __forceinline__ void mma_tf32(float* c, const uint32_t* a,
                                         uint32_t b0, uint32_t b1) {
    asm volatile(
        "mma.sync.aligned.m16n8k8.row.col.f32.tf32.tf32.f32 "
        "{%0,%1,%2,%3}, {%4,%5,%6,%7}, {%8,%9}, {%0,%1,%2,%3};"
        : "+f"(c[0]), "+f"(c[1]), "+f"(c[2]), "+f"(c[3])
        : "r"(a[0]), "r"(a[1]), "r"(a[2]), "r"(a[3]), "r"(b0), "r"(b1));
}

#define PITCH 20     // 16 k-values + 4 pad (conflict-free fragment LDS)

__global__ void __launch_bounds__(256) k_ahat(float* __restrict__ out) {
    __shared__ float sm[4 * 128 * PITCH];     // 40 KB; reused for mirror staging
    float* Ahi = sm;
    float* Alo = sm + 128 * PITCH;
    float* Bhi = sm + 2 * 128 * PITCH;
    float* Blo = sm + 3 * 128 * PITCH;

    const int bi = blockIdx.y, bj = blockIdx.x;
    if (bj < bi) return;
    const int tid  = threadIdx.x;
    const int w    = tid >> 5, lane = tid & 31;
    const int wm   = w & 1, wn = w >> 1;      // warp 64x32 region
    const int g    = lane >> 2, t = lane & 3;
    const int m0 = bi * 128, n0 = bj * 128;

    float acc[4][4][4];
#pragma unroll
    for (int a = 0; a < 4; a++)
#pragma unroll
        for (int b = 0; b < 4; b++)
#pragma unroll
            for (int r = 0; r < 4; r++) acc[a][b][r] = 0.f;

#pragma unroll
    for (int kk = 0; kk < 64; kk += 16) {
        __syncthreads();
        // stage 128 rows x 16 k of A/B hi+lo planes
#pragma unroll
        for (int i = 0; i < 2; i++) {
            int lin = tid + i * 256;          // 0..511
            int row = lin >> 2;               // 0..127
            int kq  = (lin & 3) * 4;          // 0,4,8,12
            const float4 ah = *(const float4*)(g_zhi + (size_t)(m0 + row) * 64 + kk + kq);
            const float4 al = *(const float4*)(g_zlo + (size_t)(m0 + row) * 64 + kk + kq);
            const float4 bh = *(const float4*)(g_zhi + (size_t)(n0 + row) * 64 + kk + kq);
            const float4 bl = *(const float4*)(g_zlo + (size_t)(n0 + row) * 64 + kk + kq);
            float* pa = Ahi + row * PITCH + kq;
            pa[0] = ah.x; pa[1] = ah.y; pa[2] = ah.z; pa[3] = ah.w;
            float* qa = Alo + row * PITCH + kq;
            qa[0] = al.x; qa[1] = al.y; qa[2] = al.z; qa[3] = al.w;
            float* pb = Bhi + row * PITCH + kq;
            pb[0] = bh.x; pb[1] = bh.y; pb[2] = bh.z; pb[3] = bh.w;
            float* qb = Blo + row * PITCH + kq;
            qb[0] = bl.x; qb[1] = bl.y; qb[2] = bl.z; qb[3] = bl.w;
        }
        __syncthreads();
#pragma unroll
        for (int ks = 0; ks < 16; ks += 8) {
            uint32_t ahi[4][4], alo[4][4];
#pragma unroll
            for (int mt = 0; mt < 4; mt++) {
                int r = wm * 64 + mt * 16 + g;
                const float* p = Ahi + r * PITCH + ks + t;
                ahi[mt][0] = __float_as_uint(p[0]);
                ahi[mt][1] = __float_as_uint(p[8 * PITCH]);
                ahi[mt][2] = __float_as_uint(p[4]);
                ahi[mt][3] = __float_as_uint(p[8 * PITCH + 4]);
                const float* q = Alo + r * PITCH + ks + t;
                alo[mt][0] = __float_as_uint(q[0]);
                alo[mt][1] = __float_as_uint(q[8 * PITCH]);
                alo[mt][2] = __float_as_uint(q[4]);
                alo[mt][3] = __float_as_uint(q[8 * PITCH + 4]);
            }
#pragma unroll
            for (int nt = 0; nt < 4; nt++) {
                int n = wn * 32 + nt * 8 + g;
                const float* p = Bhi + n * PITCH + ks + t;
                uint32_t bh0 = __float_as_uint(p[0]);
                uint32_t bh1 = __float_as_uint(p[4]);
                const float* q = Blo + n * PITCH + ks + t;
                uint32_t bl0 = __float_as_uint(q[0]);
                uint32_t bl1 = __float_as_uint(q[4]);
#pragma unroll
                for (int mt = 0; mt < 4; mt++) {
                    mma_tf32(acc[mt][nt], ahi[mt], bh0, bh1);
                    mma_tf32(acc[mt][nt], ahi[mt], bl0, bl1);
                    mma_tf32(acc[mt][nt], alo[mt], bh0, bh1);
                }
            }
        }
    }

    // sigmoid
#pragma unroll
    for (int mt = 0; mt < 4; mt++)
#pragma unroll
        for (int nt = 0; nt < 4; nt++)
#pragma unroll
            for (int r = 0; r < 4; r++)
                acc[mt][nt][r] = 1.0f / (1.0f + __expf(-acc[mt][nt][r]));

    // direct tile stores (float2 per fragment row)
#pragma unroll
    for (int mt = 0; mt < 4; mt++) {
        int r0 = m0 + wm * 64 + mt * 16 + g;
#pragma unroll
        for (int nt = 0; nt < 4; nt++) {
            int col = n0 + wn * 32 + nt * 8 + 2 * t;
            *(float2*)(out + (size_t)r0 * NN + col) =
                make_float2(acc[mt][nt][0], acc[mt][nt][1]);
            *(float2*)(out + (size_t)(r0 + 8) * NN + col) =
                make_float2(acc[mt][nt][2], acc[mt][nt][3]);
        }
    }
    if (bj == bi) return;

    // mirror: transpose via SMEM in two 64-col halves (pitch 136, float4 rows)
    float* st = sm;   // [64][136] = 8704 floats < 10240
#pragma unroll
    for (int h = 0; h < 2; h++) {
        __syncthreads();
        if ((wn >> 1) == h) {
            int clbase = (wn & 1) * 32;
#pragma unroll
            for (int mt = 0; mt < 4; mt++) {
                int row = wm * 64 + mt * 16 + g;
#pragma unroll
                for (int nt = 0; nt < 4; nt++) {
                    int cl = clbase + nt * 8 + 2 * t;
                    st[cl * 136 + row]           = acc[mt][nt][0];
                    st[(cl + 1) * 136 + row]     = acc[mt][nt][1];
                    st[cl * 136 + row + 8]       = acc[mt][nt][2];
                    st[(cl + 1) * 136 + row + 8] = acc[mt][nt][3];
                }
            }
        }
        __syncthreads();
#pragma unroll
        for (int p = 0; p < 8; p++) {
            int lin = p * 256 + tid;      // 0..2047
            int j  = lin >> 5;            // 0..63
            int iq = lin & 31;            // float4 index
            float4 v = *(const float4*)(st + j * 136 + iq * 4);
            *(float4*)(out + (size_t)(n0 + h * 64 + j) * NN + m0 + iq * 4) = v;
        }
    }
}

// ---------------------------------------------------------
extern "C" void kernel_launch(void* const* d_in, const int* in_sizes, int n_in,
                              void* d_out, int out_size) {
    const float* x     = (const float*)d_in[0];
    const int*   ei    = (const int*)d_in[1];
    const int*   batch = (const int*)d_in[2];
    const float* gw    = (const float*)d_in[3];
    const float* gb    = (const float*)d_in[4];
    const float* lw    = (const float*)d_in[5];
    const float* lb    = (const float*)d_in[6];
    const float* dw    = (const float*)d_in[7];
    const float* db    = (const float*)d_in[8];

    float* out     = (float*)d_out;
    float* z_node  = out;                       // [16384, 64]
    float* z_graph = out + NN * CLAT;           // [16, 64]
    float* x_hat   = z_graph + NG * CLAT;       // [16384, 128]
    float* a_hat   = x_hat + NN * CIN;          // [16384, 16384]

    k_init<<<64, 256>>>();
    k_deg<<<NE / 256, 256>>>(ei);
    k_dinv<<<NN / 256, 256>>>();
    k_self<<<NN * CIN / 256, 256>>>(x);
    k_wT<<<(CIN * CHID + CHID * CLAT) / 256 + 1, 256>>>(gw, lw);
    k_scatter<<<NE * 32 / 256, 256>>>((const float4*)x, ei);
    k_gcn<<<NN / 4, 256>>>(gb);
    k_z<<<NN / 4, 256>>>(batch, lb, z_node);
    k_split<<<NN * CLAT / 256, 256>>>(z_node);
    k_graph<<<NG, 128>>>(dw, db, z_graph);
    k_xhat<<<NN * CIN / 256, 256>>>(batch, x_hat);

    dim3 grid(128, 128);
    k_ahat<<<grid, 256>>>(a_hat);
}

// round 10
// speedup vs baseline: 1.1917x; 1.1917x over previous
#include <cuda_runtime.h>
#include <cuda_bf16.h>
#include <cstdint>

#define NN   16384
#define NE   262144
#define NG   16
#define CIN  128
#define CHID 256
#define CLAT 64

// ---- scratch (device globals; no allocation allowed) ----
__device__ float g_deg[NN];
__device__ float g_dinv[NN];
__device__ float g_aggx[NN * CIN];
__device__ float g_h[NN * CHID];
__device__ float g_wT[CIN * CHID];
__device__ float g_linT[CHID * CLAT];
__device__ float g_zsum[NG * CLAT];
__device__ float g_cnt[NG];
__device__ float g_gdec[NG * CIN];
__device__ __nv_bfloat16 g_zhi[NN * CLAT];   // bf16 hi part of z_node
__device__ __nv_bfloat16 g_zlo[NN * CLAT];   // bf16 lo part of z_node

// ---------------------------------------------------------
__global__ void k_init() {
    int i = blockIdx.x * blockDim.x + threadIdx.x;
    if (i < NN) g_deg[i] = 1.0f;
    if (i < NG * CLAT) g_zsum[i] = 0.0f;
    if (i < NG) g_cnt[i] = 0.0f;
}

__global__ void k_deg(const int* __restrict__ ei) {
    int e = blockIdx.x * blockDim.x + threadIdx.x;
    if (e < NE) atomicAdd(&g_deg[ei[NE + e]], 1.0f);
}

__global__ void k_dinv() {
    int i = blockIdx.x * blockDim.x + threadIdx.x;
    if (i < NN) g_dinv[i] = rsqrtf(g_deg[i]);
}

__global__ void k_self(const float* __restrict__ x) {
    int idx = blockIdx.x * blockDim.x + threadIdx.x;
    if (idx < NN * CIN) g_aggx[idx] = x[idx] / g_deg[idx >> 7];
}

__global__ void k_scatter(const float4* __restrict__ x4, const int* __restrict__ ei) {
    int gt = blockIdx.x * blockDim.x + threadIdx.x;
    int e = gt >> 5;
    int lane = gt & 31;
    if (e >= NE) return;
    int row = ei[e];
    int col = ei[NE + e];
    float norm = g_dinv[row] * g_dinv[col];
    float4 v = x4[row * 32 + lane];
    v.x *= norm; v.y *= norm; v.z *= norm; v.w *= norm;
    float* dst = &g_aggx[(col * 32 + lane) * 4];
    asm volatile("red.global.add.v4.f32 [%0], {%1, %2, %3, %4};"
                 :: "l"(dst), "f"(v.x), "f"(v.y), "f"(v.z), "f"(v.w) : "memory");
}

__global__ void k_wT(const float* __restrict__ gw, const float* __restrict__ lw) {
    int idx = blockIdx.x * blockDim.x + threadIdx.x;
    if (idx < CIN * CHID) {
        int h = idx >> 7, k = idx & 127;
        g_wT[k * CHID + h] = gw[idx];
    } else if (idx < CIN * CHID + CHID * CLAT) {
        int j = idx - CIN * CHID;
        int l = j >> 8, c = j & 255;
        g_linT[c * CLAT + l] = lw[j];
    }
}

__global__ void k_gcn(const float* __restrict__ gb) {
    __shared__ float sx[4][CIN];
    int i0 = blockIdx.x * 4;
    int t = threadIdx.x;
#pragma unroll
    for (int ii = 0; ii < 2; ii++) {
        int lin = t + ii * 256;
        sx[lin >> 7][lin & 127] = g_aggx[i0 * CIN + lin];
    }
    __syncthreads();
    float b = gb[t];
    float a0 = b, a1 = b, a2 = b, a3 = b;
#pragma unroll 4
    for (int k = 0; k < CIN; k++) {
        float w = g_wT[k * CHID + t];
        a0 += sx[0][k] * w;
        a1 += sx[1][k] * w;
        a2 += sx[2][k] * w;
        a3 += sx[3][k] * w;
    }
    g_h[(i0 + 0) * CHID + t] = fmaxf(a0, 0.f);
    g_h[(i0 + 1) * CHID + t] = fmaxf(a1, 0.f);
    g_h[(i0 + 2) * CHID + t] = fmaxf(a2, 0.f);
    g_h[(i0 + 3) * CHID + t] = fmaxf(a3, 0.f);
}

__global__ void k_z(const int* __restrict__ batch, const float* __restrict__ lb,
                    float* __restrict__ zout) {
    __shared__ float sA[4][CHID];
    int i0 = blockIdx.x * 4;
    int t = threadIdx.x;
#pragma unroll
    for (int ii = 0; ii < 4; ii++) {
        int lin = t + ii * 256;
        sA[lin >> 8][lin & 255] = g_h[i0 * CHID + lin];
    }
    __syncthreads();
    int j = t >> 6, c = t & 63;
    float acc = lb[c];
#pragma unroll 4
    for (int k = 0; k < CHID; k++) acc += sA[j][k] * g_linT[k * CLAT + c];
    int node = i0 + j;
    zout[node * CLAT + c] = acc;
    int b = batch[node];
    atomicAdd(&g_zsum[b * CLAT + c], acc);
    if (c == 0) atomicAdd(&g_cnt[b], 1.0f);
}

// split z into bf16 hi + bf16 lo
__global__ void k_split(const float* __restrict__ z) {
    int i = blockIdx.x * blockDim.x + threadIdx.x;
    if (i < NN * CLAT) {
        float v = z[i];
        __nv_bfloat16 h = __float2bfloat16(v);
        float lo = v - __bfloat162float(h);
        g_zhi[i] = h;
        g_zlo[i] = __float2bfloat16(lo);
    }
}

__global__ void k_graph(const float* __restrict__ dw, const float* __restrict__ db,
                        float* __restrict__ zg_out) {
    __shared__ float zg[CLAT];
    int g = blockIdx.x, t = threadIdx.x;
    if (t < CLAT) {
        float cn = fmaxf(g_cnt[g], 1.0f);
        float v = g_zsum[g * CLAT + t] / cn;
        zg[t] = v;
        zg_out[g * CLAT + t] = v;
    }
    __syncthreads();
    float acc = db[t];
#pragma unroll
    for (int l = 0; l < CLAT; l++) acc += zg[l] * dw[t * CLAT + l];
    g_gdec[g * CIN + t] = acc;
}

__global__ void k_xhat(const int* __restrict__ batch, float* __restrict__ xo) {
    int idx = blockIdx.x * blockDim.x + threadIdx.x;
    if (idx < NN * CIN) {
        int i = idx >> 7;
        xo[idx] = g_gdec[batch[i] * CIN + (idx & 127)];
    }
}

// ---------------------------------------------------------
// a_hat = sigmoid(Z Z^T): split-bf16 mma.sync m16n8k16, 3 passes
// (hi*hi + hi*lo + lo*hi; lo*lo dropped ~2^-16).
// 128x128 tile per block (8 warps, warp grid 2x4, each warp 64x32).
// Symmetric: compute upper-tri tiles; mirror via SMEM transpose.
// ---------------------------------------------------------
__device__ __forceinline__ void mma_bf16(float* c, const uint32_t* a,
                                         uint32_t b0, uint32_t b1) {
    asm volatile(
        "mma.sync.aligned.m16n8k16.row.col.f32.bf16.bf16.f32 "
        "{%0,%1,%2,%3}, {%4,%5,%6,%7}, {%8,%9}, {%0,%1,%2,%3};"
        : "+f"(c[0]), "+f"(c[1]), "+f"(c[2]), "+f"(c[3])
        : "r"(a[0]), "r"(a[1]), "r"(a[2]), "r"(a[3]), "r"(b0), "r"(b1));
}

#define PITCHB 40    // bf16 elems per row (80B = 20 banks; conflict-free quads)

__global__ void __launch_bounds__(256) k_ahat(float* __restrict__ out) {
    __shared__ __align__(16) char smbuf[4 * 128 * PITCHB * 2];  // 40960 B
    __nv_bfloat16* Ahi = (__nv_bfloat16*)smbuf;
    __nv_bfloat16* Alo = Ahi + 128 * PITCHB;
    __nv_bfloat16* Bhi = Alo + 128 * PITCHB;
    __nv_bfloat16* Blo = Bhi + 128 * PITCHB;

    const int bi = blockIdx.y, bj = blockIdx.x;
    if (bj < bi) return;
    const int tid  = threadIdx.x;
    const int w    = tid >> 5, lane = tid & 31;
    const int wm   = w & 1, wn = w >> 1;      // warp 64x32 region
    const int g    = lane >> 2, t = lane & 3;
    const int m0 = bi * 128, n0 = bj * 128;

    float acc[4][4][4];
#pragma unroll
    for (int a = 0; a < 4; a++)
#pragma unroll
        for (int b = 0; b < 4; b++)
#pragma unroll
            for (int r = 0; r < 4; r++) acc[a][b][r] = 0.f;

#pragma unroll
    for (int kk = 0; kk < 64; kk += 32) {
        __syncthreads();
        // stage 128 rows x 32 k of A/B hi+lo bf16 planes (8 bf16 = 16B per copy)
#pragma unroll
        for (int i = 0; i < 2; i++) {
            int lin = tid + i * 256;          // 0..511
            int row = lin >> 2;               // 0..127
            int seg = (lin & 3) * 8;          // 0,8,16,24
            *(float4*)(Ahi + row * PITCHB + seg) =
                *(const float4*)(g_zhi + (size_t)(m0 + row) * 64 + kk + seg);
            *(float4*)(Alo + row * PITCHB + seg) =
                *(const float4*)(g_zlo + (size_t)(m0 + row) * 64 + kk + seg);
            *(float4*)(Bhi + row * PITCHB + seg) =
                *(const float4*)(g_zhi + (size_t)(n0 + row) * 64 + kk + seg);
            *(float4*)(Blo + row * PITCHB + seg) =
                *(const float4*)(g_zlo + (size_t)(n0 + row) * 64 + kk + seg);
        }
        __syncthreads();
#pragma unroll
        for (int ks = 0; ks < 32; ks += 16) {
            uint32_t ahi[4][4], alo[4][4];
#pragma unroll
            for (int mt = 0; mt < 4; mt++) {
                int r = wm * 64 + mt * 16 + g;
                const __nv_bfloat16* p = Ahi + r * PITCHB + ks + 2 * t;
                ahi[mt][0] = *(const uint32_t*)(p);
                ahi[mt][1] = *(const uint32_t*)(p + 8 * PITCHB);
                ahi[mt][2] = *(const uint32_t*)(p + 8);
                ahi[mt][3] = *(const uint32_t*)(p + 8 * PITCHB + 8);
                const __nv_bfloat16* q = Alo + r * PITCHB + ks + 2 * t;
                alo[mt][0] = *(const uint32_t*)(q);
                alo[mt][1] = *(const uint32_t*)(q + 8 * PITCHB);
                alo[mt][2] = *(const uint32_t*)(q + 8);
                alo[mt][3] = *(const uint32_t*)(q + 8 * PITCHB + 8);
            }
#pragma unroll
            for (int nt = 0; nt < 4; nt++) {
                int n = wn * 32 + nt * 8 + g;
                const __nv_bfloat16* p = Bhi + n * PITCHB + ks + 2 * t;
                uint32_t bh0 = *(const uint32_t*)(p);
                uint32_t bh1 = *(const uint32_t*)(p + 8);
                const __nv_bfloat16* q = Blo + n * PITCHB + ks + 2 * t;
                uint32_t bl0 = *(const uint32_t*)(q);
                uint32_t bl1 = *(const uint32_t*)(q + 8);
#pragma unroll
                for (int mt = 0; mt < 4; mt++) {
                    mma_bf16(acc[mt][nt], ahi[mt], bh0, bh1);
                    mma_bf16(acc[mt][nt], ahi[mt], bl0, bl1);
                    mma_bf16(acc[mt][nt], alo[mt], bh0, bh1);
                }
            }
        }
    }

    // sigmoid
#pragma unroll
    for (int mt = 0; mt < 4; mt++)
#pragma unroll
        for (int nt = 0; nt < 4; nt++)
#pragma unroll
            for (int r = 0; r < 4; r++)
                acc[mt][nt][r] = 1.0f / (1.0f + __expf(-acc[mt][nt][r]));

    // direct tile stores (float2 per fragment row) -- validated in R7
#pragma unroll
    for (int mt = 0; mt < 4; mt++) {
        int r0 = m0 + wm * 64 + mt * 16 + g;
#pragma unroll
        for (int nt = 0; nt < 4; nt++) {
            int col = n0 + wn * 32 + nt * 8 + 2 * t;
            *(float2*)(out + (size_t)r0 * NN + col) =
                make_float2(acc[mt][nt][0], acc[mt][nt][1]);
            *(float2*)(out + (size_t)(r0 + 8) * NN + col) =
                make_float2(acc[mt][nt][2], acc[mt][nt][3]);
        }
    }
    if (bj == bi) return;

    // mirror: transpose via SMEM in two 64-col halves (pitch 136, float4 rows)
    float* st = (float*)smbuf;   // [64][136] = 34816 B <= 40960
#pragma unroll
    for (int h = 0; h < 2; h++) {
        __syncthreads();
        if ((wn >> 1) == h) {
            int clbase = (wn & 1) * 32;
#pragma unroll
            for (int mt = 0; mt < 4; mt++) {
                int row = wm * 64 + mt * 16 + g;
#pragma unroll
                for (int nt = 0; nt < 4; nt++) {
                    int cl = clbase + nt * 8 + 2 * t;
                    st[cl * 136 + row]           = acc[mt][nt][0];
                    st[(cl + 1) * 136 + row]     = acc[mt][nt][1];
                    st[cl * 136 + row + 8]       = acc[mt][nt][2];
                    st[(cl + 1) * 136 + row + 8] = acc[mt][nt][3];
                }
            }
        }
        __syncthreads();
#pragma unroll
        for (int p = 0; p < 8; p++) {
            int lin = p * 256 + tid;      // 0..2047
            int j  = lin >> 5;            // 0..63
            int iq = lin & 31;            // float4 index
            float4 v = *(const float4*)(st + j * 136 + iq * 4);
            *(float4*)(out + (size_t)(n0 + h * 64 + j) * NN + m0 + iq * 4) = v;
        }
    }
}

// ---------------------------------------------------------
extern "C" void kernel_launch(void* const* d_in, const int* in_sizes, int n_in,
                              void* d_out, int out_size) {
    const float* x     = (const float*)d_in[0];
    const int*   ei    = (const int*)d_in[1];
    const int*   batch = (const int*)d_in[2];
    const float* gw    = (const float*)d_in[3];
    const float* gb    = (const float*)d_in[4];
    const float* lw    = (const float*)d_in[5];
    const float* lb    = (const float*)d_in[6];
    const float* dw    = (const float*)d_in[7];
    const float* db    = (const float*)d_in[8];

    float* out     = (float*)d_out;
    float* z_node  = out;
    float* z_graph = out + NN * CLAT;
    float* x_hat   = z_graph + NG * CLAT;
    float* a_hat   = x_hat + NN * CIN;

    k_init<<<64, 256>>>();
    k_deg<<<NE / 256, 256>>>(ei);
    k_dinv<<<NN / 256, 256>>>();
    k_self<<<NN * CIN / 256, 256>>>(x);
    k_wT<<<(CIN * CHID + CHID * CLAT) / 256 + 1, 256>>>(gw, lw);
    k_scatter<<<NE * 32 / 256, 256>>>((const float4*)x, ei);
    k_gcn<<<NN / 4, 256>>>(gb);
    k_z<<<NN / 4, 256>>>(batch, lb, z_node);
    k_split<<<NN * CLAT / 256, 256>>>(z_node);
    k_graph<<<NG, 128>>>(dw, db, z_graph);
    k_xhat<<<NN * CIN / 256, 256>>>(batch, x_hat);

    dim3 grid(128, 128);
    k_ahat<<<grid, 256>>>(a_hat);
}